// round 17
// baseline (speedup 1.0000x reference)
#include <cuda_runtime.h>

// SpatialTransformer: trilinear warp of vol[0] ([160,192,224,2] f32) by dense
// shift field trf[0] ([160,192,224,3] f32). Reference semantics: loc clipped,
// loc0=clip(floor), loc1=clip(loc0+1), w_c0=loc1-loc.
//
// Direct-gather v3. R16 confirmed L1tex wavefront-bound with MLP (not warp
// count) as the lever: 2 vox/thread -> 83.6us at occ 47%. This version: one
// block = 4 adjacent z-rows, 224 threads, 4 voxels/thread -> 32 independent
// gathers issued back-to-back per thread. Same math throughout.

static constexpr int D0 = 160;
static constexpr int D1 = 192;
static constexpr int D2 = 224;
static constexpr int V  = 4;     // voxels per thread

__global__ __launch_bounds__(D2) void st_warp_kernel(
    const float* __restrict__ vol,   // [D0,D1,D2,2]
    const float* __restrict__ trf,   // [D0,D1,D2,3]
    float2* __restrict__ out)        // [D0,D1,D2] of float2 (2 channels)
{
    const float2* __restrict__ v2 = (const float2*)vol;

    int z    = threadIdx.x;              // 0..223
    int row0 = blockIdx.x * V;           // first of V rows
    const float mx = (float)(D0 - 1);
    const float my = (float)(D1 - 1);
    const float mz = (float)(D2 - 1);

    // ---- per-voxel state ----
    float wx0[V], wx1[V], wy0[V], wy1[V], wz0[V], wz1[V];
    int   g00[V], g01[V], g10[V], g11[V], zz0[V], zz1[V];

    #pragma unroll
    for (int v = 0; v < V; v++) {
        int row = row0 + v;
        int y = row % D1;
        int x = row / D1;
        int i = row * D2 + z;

        float sx = __ldg(&trf[3 * i + 0]);
        float sy = __ldg(&trf[3 * i + 1]);
        float sz = __ldg(&trf[3 * i + 2]);

        float lx = fminf(fmaxf((float)x + sx, 0.0f), mx);
        float ly = fminf(fmaxf((float)y + sy, 0.0f), my);
        float lz = fminf(fmaxf((float)z + sz, 0.0f), mz);

        float fx0 = floorf(lx), fy0 = floorf(ly), fz0 = floorf(lz);
        float fx1 = fminf(fx0 + 1.0f, mx);
        float fy1 = fminf(fy0 + 1.0f, my);
        float fz1 = fminf(fz0 + 1.0f, mz);

        wx0[v] = fx1 - lx;  wx1[v] = 1.0f - wx0[v];
        wy0[v] = fy1 - ly;  wy1[v] = 1.0f - wy0[v];
        wz0[v] = fz1 - lz;  wz1[v] = 1.0f - wz0[v];

        int x0 = (int)fx0, x1 = (int)fx1;
        int y0 = (int)fy0, y1 = (int)fy1;
        zz0[v] = (int)fz0;  zz1[v] = (int)fz1;

        int bx0 = x0 * D1;
        int bx1 = x1 * D1;
        g00[v] = (bx0 + y0) * D2;
        g01[v] = (bx0 + y1) * D2;
        g10[v] = (bx1 + y0) * D2;
        g11[v] = (bx1 + y1) * D2;
    }

    // ---- issue all 8*V gathers back-to-back (max MLP) ----
    float2 c[V][8];
    #pragma unroll
    for (int v = 0; v < V; v++) {
        c[v][0] = __ldg(&v2[g00[v] + zz0[v]]);
        c[v][1] = __ldg(&v2[g00[v] + zz1[v]]);
        c[v][2] = __ldg(&v2[g01[v] + zz0[v]]);
        c[v][3] = __ldg(&v2[g01[v] + zz1[v]]);
        c[v][4] = __ldg(&v2[g10[v] + zz0[v]]);
        c[v][5] = __ldg(&v2[g10[v] + zz1[v]]);
        c[v][6] = __ldg(&v2[g11[v] + zz0[v]]);
        c[v][7] = __ldg(&v2[g11[v] + zz1[v]]);
    }

    // ---- lerp trees + stores ----
    #pragma unroll
    for (int v = 0; v < V; v++) {
        float a00x = wz0[v] * c[v][0].x + wz1[v] * c[v][1].x;
        float a00y = wz0[v] * c[v][0].y + wz1[v] * c[v][1].y;
        float a01x = wz0[v] * c[v][2].x + wz1[v] * c[v][3].x;
        float a01y = wz0[v] * c[v][2].y + wz1[v] * c[v][3].y;
        float a10x = wz0[v] * c[v][4].x + wz1[v] * c[v][5].x;
        float a10y = wz0[v] * c[v][4].y + wz1[v] * c[v][5].y;
        float a11x = wz0[v] * c[v][6].x + wz1[v] * c[v][7].x;
        float a11y = wz0[v] * c[v][6].y + wz1[v] * c[v][7].y;

        float b0x = wy0[v] * a00x + wy1[v] * a01x;
        float b0y = wy0[v] * a00y + wy1[v] * a01y;
        float b1x = wy0[v] * a10x + wy1[v] * a11x;
        float b1y = wy0[v] * a10y + wy1[v] * a11y;

        float2 o;
        o.x = wx0[v] * b0x + wx1[v] * b1x;
        o.y = wx0[v] * b0y + wx1[v] * b1y;
        out[(row0 + v) * D2 + z] = o;
    }
}

extern "C" void kernel_launch(void* const* d_in, const int* in_sizes, int n_in,
                              void* d_out, int out_size)
{
    const float* vol = (const float*)d_in[0];   // [2,160,192,224,2]; batch 0 at base
    const float* trf = (const float*)d_in[1];   // [2,160,192,224,3]; batch 0 at base
    float2* out = (float2*)d_out;               // [160,192,224,2]

    st_warp_kernel<<<(D0 * D1) / V, D2>>>(vol, trf, out);   // 7680 blocks
}